// round 1
// baseline (speedup 1.0000x reference)
#include <cuda_runtime.h>
#include <cuda_bf16.h>
#include <math.h>

// Problem constants
#define BB 4
#define SS 4096
#define EE 1024
#define HH 1024
#define BSZ 128
#define NTOK (BB * SS)            // 16384 tokens
#define QKV_LD (3 * HH)           // 3072

// Scratch (device globals — no allocation allowed in kernel_launch)
__device__ float g_qkv[(size_t)NTOK * QKV_LD];   // [16384, 3072] fp32
__device__ float g_attn[(size_t)NTOK * HH];      // [16384, 1024] fp32

// ---------------------------------------------------------------------------
// Generic tiled SGEMM: C[M,N] = A[M,K] @ op(B) (+ bias)
//   TRANSB=false: B is [K,N] row-major
//   TRANSB=true : B is [N,K] row-major (C = A @ B^T)
// Tile 128x128x8, 256 threads, 8x8 register micro-tile.
// Requires M%128==0, N%128==0, K%8==0 (true for all our shapes).
// ---------------------------------------------------------------------------
template <bool TRANSB, bool BIAS>
__global__ __launch_bounds__(256, 2)
void sgemm_kernel(const float* __restrict__ A, const float* __restrict__ B,
                  const float* __restrict__ bias, float* __restrict__ C,
                  int M, int N, int K) {
    __shared__ float As[8][128];
    __shared__ float Bs[8][132];

    const int tid = threadIdx.x;
    const int bm = blockIdx.y * 128;
    const int bn = blockIdx.x * 128;
    const int ty = tid >> 4;       // 0..15
    const int tx = tid & 15;       // 0..15

    float acc[8][8];
#pragma unroll
    for (int i = 0; i < 8; i++)
#pragma unroll
        for (int j = 0; j < 8; j++) acc[i][j] = 0.0f;

    for (int k0 = 0; k0 < K; k0 += 8) {
        // --- load A tile: 128 rows x 8 k, one float4 per thread ---
        {
            int m = tid >> 1;
            int h = (tid & 1) * 4;
            const float4 a4 = *reinterpret_cast<const float4*>(
                &A[(size_t)(bm + m) * K + k0 + h]);
            As[h + 0][m] = a4.x;
            As[h + 1][m] = a4.y;
            As[h + 2][m] = a4.z;
            As[h + 3][m] = a4.w;
        }
        // --- load B tile ---
        if (!TRANSB) {
            int kk = tid >> 5;              // 0..7
            int n4 = (tid & 31) * 4;        // 0..124
            const float4 b4 = *reinterpret_cast<const float4*>(
                &B[(size_t)(k0 + kk) * N + bn + n4]);
            Bs[kk][n4 + 0] = b4.x;
            Bs[kk][n4 + 1] = b4.y;
            Bs[kk][n4 + 2] = b4.z;
            Bs[kk][n4 + 3] = b4.w;
        } else {
            int n = tid >> 1;
            int h = (tid & 1) * 4;
            const float4 b4 = *reinterpret_cast<const float4*>(
                &B[(size_t)(bn + n) * K + k0 + h]);
            Bs[h + 0][n] = b4.x;
            Bs[h + 1][n] = b4.y;
            Bs[h + 2][n] = b4.z;
            Bs[h + 3][n] = b4.w;
        }
        __syncthreads();

#pragma unroll
        for (int kk = 0; kk < 8; kk++) {
            float a[8], b[8];
#pragma unroll
            for (int i = 0; i < 8; i++) a[i] = As[kk][ty * 8 + i];
#pragma unroll
            for (int j = 0; j < 8; j++) b[j] = Bs[kk][tx * 8 + j];
#pragma unroll
            for (int i = 0; i < 8; i++)
#pragma unroll
                for (int j = 0; j < 8; j++) acc[i][j] = fmaf(a[i], b[j], acc[i][j]);
        }
        __syncthreads();
    }

    // epilogue
#pragma unroll
    for (int i = 0; i < 8; i++) {
        int m = bm + ty * 8 + i;
#pragma unroll
        for (int j = 0; j < 8; j++) {
            int n = bn + tx * 8 + j;
            float v = acc[i][j];
            if (BIAS) v += bias[n];
            C[(size_t)m * N + n] = v;
        }
    }
}

// ---------------------------------------------------------------------------
// Block-diagonal causal attention. One CTA per (batch, block) pair: 128 CTAs.
// Each CTA: scores = Qb @ Kb^T * scale (128x128, d=1024), causal mask,
// softmax (with the reference's +1e-6 eps), out = P @ Vb (128x1024).
// 256 threads, 8x8 register tiles for both GEMM phases; P lives in smem.
// ---------------------------------------------------------------------------
__global__ __launch_bounds__(256, 1)
void attn_kernel(const float* __restrict__ qkv, float* __restrict__ attn_out) {
    extern __shared__ float sm[];
    float* S  = sm;                  // 128 * 129 scores/probs
    float* T0 = sm + 128 * 129;      // tile buf 0: 16*136
    float* T1 = T0 + 16 * 136;       // tile buf 1: 16*136

    const int blk = blockIdx.x;      // 0..127 == global block index (rows contiguous)
    const float* qp = qkv + (size_t)blk * BSZ * QKV_LD;          // Q cols [0,1024)
    const float* kp = qp + HH;                                   // K cols
    const float* vp = qp + 2 * HH;                               // V cols

    const int tid = threadIdx.x;
    const int ty = tid >> 4;   // 0..15
    const int tx = tid & 15;   // 0..15

    // ---------------- Phase 1: scores = Q @ K^T ----------------
    float acc[8][8];
#pragma unroll
    for (int i = 0; i < 8; i++)
#pragma unroll
        for (int j = 0; j < 8; j++) acc[i][j] = 0.0f;

    for (int kc = 0; kc < HH; kc += 16) {
        // load Q/K chunks [128 rows x 16 dims], transposed into smem
#pragma unroll
        for (int e = 0; e < 8; e++) {
            int idx = tid + e * 256;        // 0..2047
            int r = idx >> 4;               // row 0..127
            int kk = idx & 15;              // dim 0..15
            T0[kk * 136 + r] = qp[(size_t)r * QKV_LD + kc + kk];
            T1[kk * 136 + r] = kp[(size_t)r * QKV_LD + kc + kk];
        }
        __syncthreads();
#pragma unroll
        for (int kk = 0; kk < 16; kk++) {
            float a[8], b[8];
#pragma unroll
            for (int i = 0; i < 8; i++) a[i] = T0[kk * 136 + ty * 8 + i];
#pragma unroll
            for (int j = 0; j < 8; j++) b[j] = T1[kk * 136 + tx * 8 + j];
#pragma unroll
            for (int i = 0; i < 8; i++)
#pragma unroll
                for (int j = 0; j < 8; j++) acc[i][j] = fmaf(a[i], b[j], acc[i][j]);
        }
        __syncthreads();
    }

    // write scaled + masked scores to smem
    const float scale = 0.03125f;    // 1024^-0.5
#pragma unroll
    for (int i = 0; i < 8; i++) {
        int qr = ty * 8 + i;
#pragma unroll
        for (int j = 0; j < 8; j++) {
            int kr = tx * 8 + j;
            S[qr * 129 + kr] = (kr <= qr) ? acc[i][j] * scale : -INFINITY;
        }
    }
    __syncthreads();

    // ---------------- softmax per row (threads 0..127, one row each) --------
    if (tid < 128) {
        float* row = S + tid * 129;
        float m = -INFINITY;
#pragma unroll 4
        for (int k = 0; k < 128; k++) m = fmaxf(m, row[k]);
        float s = 0.0f;
#pragma unroll 4
        for (int k = 0; k < 128; k++) {
            float e = expf(row[k] - m);     // exp(-inf - m) = 0 for masked
            row[k] = e;
            s += e;
        }
        float inv = 1.0f / (s + 1e-6f);     // reference's eps, kept faithfully
#pragma unroll 4
        for (int k = 0; k < 128; k++) row[k] *= inv;
    }
    __syncthreads();

    // ---------------- Phase 2: out = P @ V ----------------
    for (int dt = 0; dt < HH; dt += 128) {
        float o[8][8];
#pragma unroll
        for (int i = 0; i < 8; i++)
#pragma unroll
            for (int j = 0; j < 8; j++) o[i][j] = 0.0f;

        for (int kc = 0; kc < BSZ; kc += 16) {
            // load V chunk [16 k-rows x 128 d-cols]
#pragma unroll
            for (int e = 0; e < 8; e++) {
                int idx = tid + e * 256;
                int kk = idx >> 7;          // 0..15
                int d = idx & 127;          // 0..127
                T0[kk * 136 + d] = vp[(size_t)(kc + kk) * QKV_LD + dt + d];
            }
            __syncthreads();
#pragma unroll
            for (int kk = 0; kk < 16; kk++) {
                float p[8], v[8];
#pragma unroll
                for (int i = 0; i < 8; i++) p[i] = S[(ty * 8 + i) * 129 + kc + kk];
#pragma unroll
                for (int j = 0; j < 8; j++) v[j] = T0[kk * 136 + tx * 8 + j];
#pragma unroll
                for (int i = 0; i < 8; i++)
#pragma unroll
                    for (int j = 0; j < 8; j++) o[i][j] = fmaf(p[i], v[j], o[i][j]);
            }
            __syncthreads();
        }

        // write out tile
#pragma unroll
        for (int i = 0; i < 8; i++) {
            int row = blk * BSZ + ty * 8 + i;
#pragma unroll
            for (int j = 0; j < 8; j++) {
                attn_out[(size_t)row * HH + dt + tx * 8 + j] = o[i][j];
            }
        }
        __syncthreads();
    }
}

// ---------------------------------------------------------------------------
extern "C" void kernel_launch(void* const* d_in, const int* in_sizes, int n_in,
                              void* d_out, int out_size) {
    const float* x     = (const float*)d_in[0];   // [4,4096,1024]
    const float* Wqkv  = (const float*)d_in[1];   // [1024,3072]
    const float* Wout  = (const float*)d_in[2];   // [1024,1024]
    const float* bout  = (const float*)d_in[3];   // [1024]
    float* out = (float*)d_out;                   // [4,4096,1024]

    float* qkv = nullptr;
    float* attn = nullptr;
    cudaGetSymbolAddress((void**)&qkv, g_qkv);
    cudaGetSymbolAddress((void**)&attn, g_attn);

    // GEMM1: qkv = x @ W_qkv   [16384,3072]
    {
        dim3 grid(QKV_LD / 128, NTOK / 128);
        sgemm_kernel<false, false><<<grid, 256>>>(x, Wqkv, nullptr, qkv,
                                                  NTOK, QKV_LD, EE);
    }

    // Attention: 128 block-diagonal tiles
    {
        const int smem = (128 * 129 + 2 * 16 * 136) * (int)sizeof(float); // 83456 B
        cudaFuncSetAttribute(attn_kernel, cudaFuncAttributeMaxDynamicSharedMemorySize,
                             smem);
        attn_kernel<<<BB * (SS / BSZ), 256, smem>>>(qkv, attn);
    }

    // GEMM3: out = attn @ W_out^T + b_out   [16384,1024]
    {
        dim3 grid(HH / 128, NTOK / 128);
        sgemm_kernel<true, true><<<grid, 256>>>(attn, Wout, bout, out,
                                                NTOK, HH, HH);
    }
}

// round 2
// speedup vs baseline: 2.9125x; 2.9125x over previous
#include <cuda_runtime.h>
#include <cuda_bf16.h>
#include <math.h>
#include <stdint.h>

// Problem constants
#define BB 4
#define SS 4096
#define EE 1024
#define HH 1024
#define BSZ 128
#define NTOK (BB * SS)            // 16384 tokens
#define QKV_LD (3 * HH)           // 3072

// Scratch (device globals — no allocation allowed)
__device__ float g_qkv[(size_t)NTOK * QKV_LD];    // [16384, 3072] fp32 (exact)
__device__ float g_attn[(size_t)NTOK * HH];       // [16384, 1024] tf32-rounded
__device__ float g_xr[(size_t)NTOK * EE];         // x rounded to tf32
__device__ float g_wqkvr[(size_t)EE * QKV_LD];    // W_qkv rounded
__device__ float g_woutr[(size_t)HH * HH];        // W_out rounded

// ---------------------------------------------------------------------------
// helpers
// ---------------------------------------------------------------------------
__device__ __forceinline__ uint32_t f2tf32(float x) {
    uint32_t o;
    asm("cvt.rna.tf32.f32 %0, %1;" : "=r"(o) : "f"(x));
    return o;
}

__device__ __forceinline__ void cp16(uint32_t smem_dst, const void* gptr) {
    asm volatile("cp.async.cg.shared.global [%0], [%1], 16;\n"
                 :: "r"(smem_dst), "l"(gptr));
}
__device__ __forceinline__ void cp_commit() {
    asm volatile("cp.async.commit_group;\n");
}
template <int N>
__device__ __forceinline__ void cp_wait() {
    asm volatile("cp.async.wait_group %0;\n" :: "n"(N));
}

__device__ __forceinline__ void mma_tf32(float c[4], const uint32_t a[4],
                                         const uint32_t b[2]) {
    asm volatile(
        "mma.sync.aligned.m16n8k8.row.col.f32.tf32.tf32.f32 "
        "{%0,%1,%2,%3}, {%4,%5,%6,%7}, {%8,%9}, {%0,%1,%2,%3};\n"
        : "+f"(c[0]), "+f"(c[1]), "+f"(c[2]), "+f"(c[3])
        : "r"(a[0]), "r"(a[1]), "r"(a[2]), "r"(a[3]), "r"(b[0]), "r"(b[1]));
}

// ---------------------------------------------------------------------------
// round-to-tf32 kernel (n % 4 == 0)
// ---------------------------------------------------------------------------
__global__ void round_tf32_kernel(const float* __restrict__ in,
                                  float* __restrict__ out, int n4) {
    int i = blockIdx.x * blockDim.x + threadIdx.x;
    int stride = gridDim.x * blockDim.x;
    for (; i < n4; i += stride) {
        float4 v = reinterpret_cast<const float4*>(in)[i];
        float4 o;
        o.x = __uint_as_float(f2tf32(v.x));
        o.y = __uint_as_float(f2tf32(v.y));
        o.z = __uint_as_float(f2tf32(v.z));
        o.w = __uint_as_float(f2tf32(v.w));
        reinterpret_cast<float4*>(out)[i] = o;
    }
}

// ---------------------------------------------------------------------------
// tf32 tensor-core GEMM: C[M,N] = A[M,K] @ op(B) (+ bias)
//   TRANSB=false: B[K,N];  TRANSB=true: B[N,K] (C = A @ B^T)
// Inputs A,B must already be tf32-rounded fp32.
// 128x128x32 tile, 256 thr, warp grid 4(M)x2(N), warp tile 32x64 of m16n8k8.
// Double-buffered cp.async. All dims multiples of 128 / K mult of 32.
// ---------------------------------------------------------------------------
#define SA 36     // A smem row stride (floats): banks (4g+tig) conflict-free
#define SB 136    // B smem row stride (non-trans)
#define ASZ (128 * SA)        // per-stage A floats
#define BSZ_NT (32 * SB)      // per-stage B floats (non-trans)
#define BSZ_T (128 * SA)      // per-stage B floats (trans)

template <bool TRANSB, bool BIAS>
__global__ __launch_bounds__(256)
void mma_gemm_kernel(const float* __restrict__ A, const float* __restrict__ B,
                     const float* __restrict__ bias, float* __restrict__ C,
                     int M, int N, int K) {
    extern __shared__ float sm[];
    float* As = sm;
    float* Bs = sm + 2 * ASZ;

    const int tid = threadIdx.x;
    const int warp = tid >> 5;
    const int lane = tid & 31;
    const int g = lane >> 2;       // group 0..7
    const int tig = lane & 3;      // 0..3
    const int wm = (warp & 3) * 32;
    const int wn = (warp >> 2) * 64;
    const int bm = blockIdx.y * 128;
    const int bn = blockIdx.x * 128;

    const uint32_t sA = (uint32_t)__cvta_generic_to_shared(As);
    const uint32_t sB = (uint32_t)__cvta_generic_to_shared(Bs);
    const uint32_t* uAs = reinterpret_cast<const uint32_t*>(As);
    const uint32_t* uBs = reinterpret_cast<const uint32_t*>(Bs);

    float acc[2][8][4];
#pragma unroll
    for (int mi = 0; mi < 2; mi++)
#pragma unroll
        for (int nj = 0; nj < 8; nj++)
#pragma unroll
            for (int r = 0; r < 4; r++) acc[mi][nj][r] = 0.0f;

    // ---- stage loaders ----
    auto loadA = [&](int k0, int stage) {
#pragma unroll
        for (int i = 0; i < 4; i++) {
            int idx = tid + i * 256;         // 0..1023
            int row = idx >> 3;              // 0..127
            int c = idx & 7;                 // 16B chunk
            cp16(sA + (uint32_t)(stage * ASZ + row * SA + c * 4) * 4,
                 &A[(size_t)(bm + row) * K + k0 + c * 4]);
        }
    };
    auto loadB = [&](int k0, int stage) {
        if (!TRANSB) {
#pragma unroll
            for (int i = 0; i < 4; i++) {
                int idx = tid + i * 256;
                int row = idx >> 5;          // 0..31 (k)
                int c = idx & 31;            // 0..31 (n/4)
                cp16(sB + (uint32_t)(stage * BSZ_NT + row * SB + c * 4) * 4,
                     &B[(size_t)(k0 + row) * N + bn + c * 4]);
            }
        } else {
#pragma unroll
            for (int i = 0; i < 4; i++) {
                int idx = tid + i * 256;
                int row = idx >> 3;          // 0..127 (n)
                int c = idx & 7;
                cp16(sB + (uint32_t)(stage * BSZ_T + row * SA + c * 4) * 4,
                     &B[(size_t)(bn + row) * K + k0 + c * 4]);
            }
        }
    };

    auto compute = [&](int stage) {
        const uint32_t* pa = uAs + stage * ASZ;
        const uint32_t* pb = uBs + stage * (TRANSB ? BSZ_T : BSZ_NT);
#pragma unroll
        for (int kf = 0; kf < 4; kf++) {
            const int k = kf * 8;
            uint32_t a[2][4];
#pragma unroll
            for (int mi = 0; mi < 2; mi++) {
                int m0 = wm + mi * 16 + g;
                a[mi][0] = pa[m0 * SA + k + tig];
                a[mi][1] = pa[(m0 + 8) * SA + k + tig];
                a[mi][2] = pa[m0 * SA + k + tig + 4];
                a[mi][3] = pa[(m0 + 8) * SA + k + tig + 4];
            }
            uint32_t b[8][2];
#pragma unroll
            for (int nj = 0; nj < 8; nj++) {
                int n = wn + nj * 8 + g;
                if (!TRANSB) {
                    b[nj][0] = pb[(k + tig) * SB + n];
                    b[nj][1] = pb[(k + tig + 4) * SB + n];
                } else {
                    b[nj][0] = pb[n * SA + k + tig];
                    b[nj][1] = pb[n * SA + k + tig + 4];
                }
            }
#pragma unroll
            for (int mi = 0; mi < 2; mi++)
#pragma unroll
                for (int nj = 0; nj < 8; nj++)
                    mma_tf32(acc[mi][nj], a[mi], b[nj]);
        }
    };

    // ---- pipelined main loop ----
    const int T = K / 32;
    loadA(0, 0);
    loadB(0, 0);
    cp_commit();
    for (int t = 0; t < T; t++) {
        int buf = t & 1;
        if (t + 1 < T) {
            loadA((t + 1) * 32, buf ^ 1);
            loadB((t + 1) * 32, buf ^ 1);
            cp_commit();
            cp_wait<1>();
        } else {
            cp_wait<0>();
        }
        __syncthreads();
        compute(buf);
        __syncthreads();
    }

    // ---- epilogue ----
#pragma unroll
    for (int mi = 0; mi < 2; mi++) {
        int m0 = bm + wm + mi * 16 + g;
#pragma unroll
        for (int nj = 0; nj < 8; nj++) {
            int n = bn + wn + nj * 8 + tig * 2;
            float bv0 = BIAS ? bias[n] : 0.0f;
            float bv1 = BIAS ? bias[n + 1] : 0.0f;
            float2 r0 = make_float2(acc[mi][nj][0] + bv0, acc[mi][nj][1] + bv1);
            float2 r1 = make_float2(acc[mi][nj][2] + bv0, acc[mi][nj][3] + bv1);
            *reinterpret_cast<float2*>(&C[(size_t)m0 * N + n]) = r0;
            *reinterpret_cast<float2*>(&C[(size_t)(m0 + 8) * N + n]) = r1;
        }
    }
}

// ---------------------------------------------------------------------------
// Block-diagonal causal attention (fp32). One CTA per (batch, block): 128 CTAs.
// Output is tf32-rounded (it feeds the tf32 GEMM3).
// ---------------------------------------------------------------------------
__global__ __launch_bounds__(256, 1)
void attn_kernel(const float* __restrict__ qkv, float* __restrict__ attn_out) {
    extern __shared__ float smf[];
    float* S  = smf;                 // 128 * 129
    float* T0 = smf + 128 * 129;     // 16*136
    float* T1 = T0 + 16 * 136;

    const int blk = blockIdx.x;
    const float* qp = qkv + (size_t)blk * BSZ * QKV_LD;
    const float* kp = qp + HH;
    const float* vp = qp + 2 * HH;

    const int tid = threadIdx.x;
    const int ty = tid >> 4;
    const int tx = tid & 15;

    float acc[8][8];
#pragma unroll
    for (int i = 0; i < 8; i++)
#pragma unroll
        for (int j = 0; j < 8; j++) acc[i][j] = 0.0f;

    for (int kc = 0; kc < HH; kc += 16) {
#pragma unroll
        for (int e = 0; e < 8; e++) {
            int idx = tid + e * 256;
            int r = idx >> 4;
            int kk = idx & 15;
            T0[kk * 136 + r] = qp[(size_t)r * QKV_LD + kc + kk];
            T1[kk * 136 + r] = kp[(size_t)r * QKV_LD + kc + kk];
        }
        __syncthreads();
#pragma unroll
        for (int kk = 0; kk < 16; kk++) {
            float a[8], b[8];
#pragma unroll
            for (int i = 0; i < 8; i++) a[i] = T0[kk * 136 + ty * 8 + i];
#pragma unroll
            for (int j = 0; j < 8; j++) b[j] = T1[kk * 136 + tx * 8 + j];
#pragma unroll
            for (int i = 0; i < 8; i++)
#pragma unroll
                for (int j = 0; j < 8; j++) acc[i][j] = fmaf(a[i], b[j], acc[i][j]);
        }
        __syncthreads();
    }

    const float scale = 0.03125f;
#pragma unroll
    for (int i = 0; i < 8; i++) {
        int qr = ty * 8 + i;
#pragma unroll
        for (int j = 0; j < 8; j++) {
            int kr = tx * 8 + j;
            S[qr * 129 + kr] = (kr <= qr) ? acc[i][j] * scale : -INFINITY;
        }
    }
    __syncthreads();

    if (tid < 128) {
        float* row = S + tid * 129;
        float m = -INFINITY;
#pragma unroll 4
        for (int k = 0; k < 128; k++) m = fmaxf(m, row[k]);
        float s = 0.0f;
#pragma unroll 4
        for (int k = 0; k < 128; k++) {
            float e = expf(row[k] - m);
            row[k] = e;
            s += e;
        }
        float inv = 1.0f / (s + 1e-6f);
#pragma unroll 4
        for (int k = 0; k < 128; k++) row[k] *= inv;
    }
    __syncthreads();

    for (int dt = 0; dt < HH; dt += 128) {
        float o[8][8];
#pragma unroll
        for (int i = 0; i < 8; i++)
#pragma unroll
            for (int j = 0; j < 8; j++) o[i][j] = 0.0f;

        for (int kc = 0; kc < BSZ; kc += 16) {
#pragma unroll
            for (int e = 0; e < 8; e++) {
                int idx = tid + e * 256;
                int kk = idx >> 7;
                int d = idx & 127;
                T0[kk * 136 + d] = vp[(size_t)(kc + kk) * QKV_LD + dt + d];
            }
            __syncthreads();
#pragma unroll
            for (int kk = 0; kk < 16; kk++) {
                float p[8], v[8];
#pragma unroll
                for (int i = 0; i < 8; i++) p[i] = S[(ty * 8 + i) * 129 + kc + kk];
#pragma unroll
                for (int j = 0; j < 8; j++) v[j] = T0[kk * 136 + tx * 8 + j];
#pragma unroll
                for (int i = 0; i < 8; i++)
#pragma unroll
                    for (int j = 0; j < 8; j++) o[i][j] = fmaf(p[i], v[j], o[i][j]);
            }
            __syncthreads();
        }

#pragma unroll
        for (int i = 0; i < 8; i++) {
            int row = blk * BSZ + ty * 8 + i;
#pragma unroll
            for (int j = 0; j < 8; j++) {
                // round to tf32 here: GEMM3 consumes this as a tf32 operand
                attn_out[(size_t)row * HH + dt + tx * 8 + j] =
                    __uint_as_float(f2tf32(o[i][j]));
            }
        }
        __syncthreads();
    }
}

// ---------------------------------------------------------------------------
extern "C" void kernel_launch(void* const* d_in, const int* in_sizes, int n_in,
                              void* d_out, int out_size) {
    const float* x    = (const float*)d_in[0];
    const float* Wqkv = (const float*)d_in[1];
    const float* Wout = (const float*)d_in[2];
    const float* bout = (const float*)d_in[3];
    float* out = (float*)d_out;

    float *qkv, *attn, *xr, *wqkvr, *woutr;
    cudaGetSymbolAddress((void**)&qkv, g_qkv);
    cudaGetSymbolAddress((void**)&attn, g_attn);
    cudaGetSymbolAddress((void**)&xr, g_xr);
    cudaGetSymbolAddress((void**)&wqkvr, g_wqkvr);
    cudaGetSymbolAddress((void**)&woutr, g_woutr);

    // round GEMM inputs to tf32 (round-to-nearest; HW mma truncates otherwise)
    round_tf32_kernel<<<2048, 256>>>(x, xr, (NTOK * EE) / 4);
    round_tf32_kernel<<<1024, 256>>>(Wqkv, wqkvr, (EE * QKV_LD) / 4);
    round_tf32_kernel<<<512, 256>>>(Wout, woutr, (HH * HH) / 4);

    // GEMM1: qkv = xr @ wqkvr  [16384, 3072]
    {
        const int smem = (2 * ASZ + 2 * BSZ_NT) * (int)sizeof(float); // 71680
        cudaFuncSetAttribute(mma_gemm_kernel<false, false>,
                             cudaFuncAttributeMaxDynamicSharedMemorySize, smem);
        dim3 grid(QKV_LD / 128, NTOK / 128);
        mma_gemm_kernel<false, false><<<grid, 256, smem>>>(
            xr, wqkvr, nullptr, qkv, NTOK, QKV_LD, EE);
    }

    // Attention (fp32 math, tf32-rounded output)
    {
        const int smem = (128 * 129 + 2 * 16 * 136) * (int)sizeof(float);
        cudaFuncSetAttribute(attn_kernel,
                             cudaFuncAttributeMaxDynamicSharedMemorySize, smem);
        attn_kernel<<<BB * (SS / BSZ), 256, smem>>>(qkv, attn);
    }

    // GEMM3: out = attn @ woutr^T + bout  [16384, 1024]
    {
        const int smem = (2 * ASZ + 2 * BSZ_T) * (int)sizeof(float); // 73728
        cudaFuncSetAttribute(mma_gemm_kernel<true, true>,
                             cudaFuncAttributeMaxDynamicSharedMemorySize, smem);
        dim3 grid(HH / 128, NTOK / 128);
        mma_gemm_kernel<true, true><<<grid, 256, smem>>>(
            attn, woutr, bout, out, NTOK, HH, HH);
    }
}

// round 4
// speedup vs baseline: 6.5051x; 2.2335x over previous
#include <cuda_runtime.h>
#include <cuda_fp16.h>
#include <math.h>
#include <stdint.h>

// Problem constants
#define BB 4
#define SS 4096
#define EE 1024
#define HH 1024
#define NTOK (BB * SS)            // 16384
#define QKV_LD (3 * HH)           // 3072

// Scratch (device globals)
__device__ __half g_qkvh[(size_t)NTOK * QKV_LD];   // GEMM1 out / attn in (fp16)
__device__ __half g_attnh[(size_t)NTOK * HH];      // attn out / GEMM3 A (fp16)
__device__ __half g_xh[(size_t)NTOK * EE];         // x fp16
__device__ __half g_wqkvt[(size_t)QKV_LD * EE];    // W_qkv^T fp16 [3072][1024]
__device__ __half g_wouth[(size_t)HH * HH];        // W_out fp16 [1024][1024] ([n][k])

// ---------------------------------------------------------------------------
// helpers
// ---------------------------------------------------------------------------
__device__ __forceinline__ uint32_t smem_u32(const void* p) {
    return (uint32_t)__cvta_generic_to_shared(p);
}
__device__ __forceinline__ void cp16(uint32_t dst, const void* g) {
    asm volatile("cp.async.cg.shared.global [%0], [%1], 16;\n" :: "r"(dst), "l"(g));
}
__device__ __forceinline__ void cp_commit() {
    asm volatile("cp.async.commit_group;\n");
}
template <int N> __device__ __forceinline__ void cp_wait() {
    asm volatile("cp.async.wait_group %0;\n" :: "n"(N));
}

// fp16 mma, fp32 accumulate: D = A(16x16) * B(16x8) + D
__device__ __forceinline__ void mma_f16(float c[4], const uint32_t a[4],
                                        const uint32_t b[2]) {
    asm volatile(
        "mma.sync.aligned.m16n8k16.row.col.f32.f16.f16.f32 "
        "{%0,%1,%2,%3}, {%4,%5,%6,%7}, {%8,%9}, {%0,%1,%2,%3};\n"
        : "+f"(c[0]), "+f"(c[1]), "+f"(c[2]), "+f"(c[3])
        : "r"(a[0]), "r"(a[1]), "r"(a[2]), "r"(a[3]), "r"(b[0]), "r"(b[1]));
}

__device__ __forceinline__ void ldsm_x4_t(uint32_t& r0, uint32_t& r1,
                                          uint32_t& r2, uint32_t& r3, uint32_t a) {
    asm volatile("ldmatrix.sync.aligned.m8n8.x4.trans.shared.b16 {%0,%1,%2,%3}, [%4];"
                 : "=r"(r0), "=r"(r1), "=r"(r2), "=r"(r3) : "r"(a));
}

// ---------------------------------------------------------------------------
// conversions
// ---------------------------------------------------------------------------
__global__ void cvt_half_kernel(const float* __restrict__ in,
                                __half* __restrict__ out, int n4) {
    int i = blockIdx.x * blockDim.x + threadIdx.x;
    int stride = gridDim.x * blockDim.x;
    for (; i < n4; i += stride) {
        float4 v = reinterpret_cast<const float4*>(in)[i];
        reinterpret_cast<__half2*>(out)[i * 2 + 0] = __floats2half2_rn(v.x, v.y);
        reinterpret_cast<__half2*>(out)[i * 2 + 1] = __floats2half2_rn(v.z, v.w);
    }
}

__global__ void transpose_cvt_kernel(const float* __restrict__ in,
                                     __half* __restrict__ out, int R, int C) {
    __shared__ float t[32][33];
    int bx = blockIdx.x * 32;   // C
    int by = blockIdx.y * 32;   // R
#pragma unroll
    for (int i = threadIdx.y; i < 32; i += 8)
        t[i][threadIdx.x] = in[(size_t)(by + i) * C + bx + threadIdx.x];
    __syncthreads();
#pragma unroll
    for (int i = threadIdx.y; i < 32; i += 8)
        out[(size_t)(bx + i) * R + by + threadIdx.x] = __float2half_rn(t[threadIdx.x][i]);
}

// ---------------------------------------------------------------------------
// fp16 tensor GEMM: C[M,N] = A[M,K] @ B[N,K]^T (+bias), fp32 accumulate.
// A,B fp16 row-major, K contiguous. Tile 128x256x64, 8 warps (2Mx4N),
// warp tile 64x64, 3-stage cp.async.
// smem per stage: A 128x144B + B 256x144B = 55296B (stride 72 halfs=36 words).
// ---------------------------------------------------------------------------
#define G_STG 55296
#define G_SMEM (3 * G_STG)

template <bool OUTHALF, bool BIAS>
__global__ __launch_bounds__(256, 1)
void hgemm_kernel(const __half* __restrict__ A, const __half* __restrict__ B,
                  const float* __restrict__ bias, void* __restrict__ Cv,
                  int M, int N, int K) {
    extern __shared__ char sm[];
    const uint32_t smb = smem_u32(sm);
    const int tid = threadIdx.x;
    const int warp = tid >> 5;
    const int lane = tid & 31;
    const int g = lane >> 2;
    const int tig = lane & 3;
    const int wm = (warp >> 2) * 64;     // 0 / 64
    const int wn = (warp & 3) * 64;      // 0..192
    const int bm = blockIdx.y * 128;
    const int bn = blockIdx.x * 256;

    float acc[4][8][4];
#pragma unroll
    for (int mi = 0; mi < 4; mi++)
#pragma unroll
        for (int nj = 0; nj < 8; nj++)
#pragma unroll
            for (int r = 0; r < 4; r++) acc[mi][nj][r] = 0.0f;

    auto fill = [&](int t) {
        const uint32_t sa = smb + (t % 3) * G_STG;
        const uint32_t sb = sa + 128 * 144;
        const int k0 = t * 64;
#pragma unroll
        for (int i = 0; i < 4; i++) {        // A: 128 rows x 8 chunks
            int idx = tid + i * 256;
            int r = idx >> 3, c = idx & 7;
            cp16(sa + r * 144 + c * 16, &A[(size_t)(bm + r) * K + k0 + c * 8]);
        }
#pragma unroll
        for (int i = 0; i < 8; i++) {        // B: 256 rows x 8 chunks
            int idx = tid + i * 256;
            int r = idx >> 3, c = idx & 7;
            cp16(sb + r * 144 + c * 16, &B[(size_t)(bn + r) * K + k0 + c * 8]);
        }
    };

    const int T = K / 64;
    fill(0); cp_commit();
    fill(1); cp_commit();

    for (int t = 0; t < T; t++) {
        if (t + 2 < T) fill(t + 2);
        cp_commit();
        cp_wait<2>();
        __syncthreads();

        const uint32_t* pa = reinterpret_cast<const uint32_t*>(sm + (t % 3) * G_STG);
        const uint32_t* pb = pa + (128 * 144) / 4;
#pragma unroll
        for (int kf = 0; kf < 4; kf++) {
            const int kw = kf * 8;
            uint32_t a[4][4];
#pragma unroll
            for (int mi = 0; mi < 4; mi++) {
                int m0 = wm + mi * 16 + g;
                a[mi][0] = pa[m0 * 36 + kw + tig];
                a[mi][1] = pa[(m0 + 8) * 36 + kw + tig];
                a[mi][2] = pa[m0 * 36 + kw + tig + 4];
                a[mi][3] = pa[(m0 + 8) * 36 + kw + tig + 4];
            }
            uint32_t b[8][2];
#pragma unroll
            for (int nj = 0; nj < 8; nj++) {
                int n = wn + nj * 8 + g;
                b[nj][0] = pb[n * 36 + kw + tig];
                b[nj][1] = pb[n * 36 + kw + tig + 4];
            }
#pragma unroll
            for (int mi = 0; mi < 4; mi++)
#pragma unroll
                for (int nj = 0; nj < 8; nj++) mma_f16(acc[mi][nj], a[mi], b[nj]);
        }
        __syncthreads();
    }

    // epilogue
#pragma unroll
    for (int mi = 0; mi < 4; mi++) {
        int r0 = bm + wm + mi * 16 + g;
#pragma unroll
        for (int nj = 0; nj < 8; nj++) {
            int n = bn + wn + nj * 8 + tig * 2;
            float c0 = acc[mi][nj][0], c1 = acc[mi][nj][1];
            float c2 = acc[mi][nj][2], c3 = acc[mi][nj][3];
            if (BIAS) {
                float b0 = bias[n], b1 = bias[n + 1];
                c0 += b0; c1 += b1; c2 += b0; c3 += b1;
            }
            if (OUTHALF) {
                __half* C = (__half*)Cv;
                *reinterpret_cast<__half2*>(&C[(size_t)r0 * N + n]) =
                    __floats2half2_rn(c0, c1);
                *reinterpret_cast<__half2*>(&C[(size_t)(r0 + 8) * N + n]) =
                    __floats2half2_rn(c2, c3);
            } else {
                float* C = (float*)Cv;
                *reinterpret_cast<float2*>(&C[(size_t)r0 * N + n]) = make_float2(c0, c1);
                *reinterpret_cast<float2*>(&C[(size_t)(r0 + 8) * N + n]) = make_float2(c2, c3);
            }
        }
    }
}

// ---------------------------------------------------------------------------
// Block-diagonal causal attention on tensor cores.
// One CTA per (batch, block): 128 CTAs, 256 threads (8 warps).
// Phase1: S = Q@K^T (fp16 mma, fp32 acc), warp grid 4Mx2N (tile 32x64).
// fp32 softmax (+1e-6 eps). Phase2: O = P@V, V fragments via ldmatrix.trans.
// smem: S fp32 128x132 | two 36864B stage buffers (QK then V) | P fp16 128x136.
// ---------------------------------------------------------------------------
#define A_S_BYTES (128 * 132 * 4)                 // 67584
#define A_STG 36864
#define A_P_OFF (A_S_BYTES + 2 * A_STG)           // 141312
#define A_SMEM (A_P_OFF + 128 * 136 * 2)          // 176128

__global__ __launch_bounds__(256, 1)
void attn_tc_kernel(const __half* __restrict__ qkv, __half* __restrict__ attn_out) {
    extern __shared__ char sm[];
    float* S = (float*)sm;
    const uint32_t smb = smem_u32(sm);
    const uint32_t stg0 = smb + A_S_BYTES;
    const uint32_t pbase = smb + A_P_OFF;

    const int blk = blockIdx.x;
    const __half* qp = qkv + (size_t)blk * 128 * QKV_LD;
    const __half* kp = qp + HH;
    const __half* vp = qp + 2 * HH;

    const int tid = threadIdx.x;
    const int warp = tid >> 5;
    const int lane = tid & 31;
    const int g = lane >> 2;
    const int tig = lane & 3;
    const int wm = (warp & 3) * 32;      // 0..96
    const int wn = (warp >> 2) * 64;     // 0 / 64

    // ---------------- Phase 1: S = Q @ K^T ----------------
    float acc[2][8][4];
#pragma unroll
    for (int mi = 0; mi < 2; mi++)
#pragma unroll
        for (int nj = 0; nj < 8; nj++)
#pragma unroll
            for (int r = 0; r < 4; r++) acc[mi][nj][r] = 0.0f;

    auto fillQK = [&](int t) {
        const uint32_t qs = stg0 + (t & 1) * A_STG;
        const uint32_t ks = qs + 128 * 144;
        const int k0 = t * 64;
#pragma unroll
        for (int i = 0; i < 4; i++) {
            int idx = tid + i * 256;
            int r = idx >> 3, c = idx & 7;
            cp16(qs + r * 144 + c * 16, &qp[(size_t)r * QKV_LD + k0 + c * 8]);
            cp16(ks + r * 144 + c * 16, &kp[(size_t)r * QKV_LD + k0 + c * 8]);
        }
    };

    fillQK(0); cp_commit();
    for (int t = 0; t < 16; t++) {
        if (t + 1 < 16) fillQK(t + 1);
        cp_commit();
        cp_wait<1>();
        __syncthreads();

        const uint32_t* pq = reinterpret_cast<const uint32_t*>(sm + A_S_BYTES + (t & 1) * A_STG);
        const uint32_t* pk = pq + (128 * 144) / 4;
#pragma unroll
        for (int kf = 0; kf < 4; kf++) {
            const int kw = kf * 8;
            uint32_t a[2][4];
#pragma unroll
            for (int mi = 0; mi < 2; mi++) {
                int m0 = wm + mi * 16 + g;
                a[mi][0] = pq[m0 * 36 + kw + tig];
                a[mi][1] = pq[(m0 + 8) * 36 + kw + tig];
                a[mi][2] = pq[m0 * 36 + kw + tig + 4];
                a[mi][3] = pq[(m0 + 8) * 36 + kw + tig + 4];
            }
            uint32_t b[8][2];
#pragma unroll
            for (int nj = 0; nj < 8; nj++) {
                int n = wn + nj * 8 + g;
                b[nj][0] = pk[n * 36 + kw + tig];
                b[nj][1] = pk[n * 36 + kw + tig + 4];
            }
#pragma unroll
            for (int mi = 0; mi < 2; mi++)
#pragma unroll
                for (int nj = 0; nj < 8; nj++) mma_f16(acc[mi][nj], a[mi], b[nj]);
        }
        __syncthreads();
    }

    // scale + causal mask -> S (fp32, stride 132)
    const float scale = 0.03125f;
#pragma unroll
    for (int mi = 0; mi < 2; mi++) {
        int r0 = wm + mi * 16 + g;
        int r1 = r0 + 8;
#pragma unroll
        for (int nj = 0; nj < 8; nj++) {
            int c = wn + nj * 8 + tig * 2;
            S[r0 * 132 + c]     = (c     <= r0) ? acc[mi][nj][0] * scale : -INFINITY;
            S[r0 * 132 + c + 1] = (c + 1 <= r0) ? acc[mi][nj][1] * scale : -INFINITY;
            S[r1 * 132 + c]     = (c     <= r1) ? acc[mi][nj][2] * scale : -INFINITY;
            S[r1 * 132 + c + 1] = (c + 1 <= r1) ? acc[mi][nj][3] * scale : -INFINITY;
        }
    }
    __syncthreads();

    // softmax (rows 0..127), write P fp16 (stride 136 halfs)
    if (tid < 128) {
        const float* row = S + tid * 132;
        float m = -INFINITY;
#pragma unroll 4
        for (int k = 0; k < 128; k++) m = fmaxf(m, row[k]);
        float s = 0.0f;
        float e[128];
#pragma unroll 4
        for (int k = 0; k < 128; k++) {
            e[k] = expf(row[k] - m);
            s += e[k];
        }
        float inv = 1.0f / (s + 1e-6f);
        __half2* prow = reinterpret_cast<__half2*>(sm + A_P_OFF + tid * 272);
#pragma unroll 4
        for (int k = 0; k < 128; k += 2)
            prow[k / 2] = __floats2half2_rn(e[k] * inv, e[k + 1] * inv);
    }
    __syncthreads();

    // ---------------- Phase 2: O = P @ V ----------------
    auto fillV = [&](int c) {
        const uint32_t vs = stg0 + (c & 1) * A_STG;
#pragma unroll
        for (int i = 0; i < 8; i++) {
            int idx = tid + i * 256;
            int r = idx >> 4, ch = idx & 15;
            cp16(vs + r * 272 + ch * 16, &vp[(size_t)r * QKV_LD + c * 128 + ch * 8]);
        }
    };

    const uint32_t* pp = reinterpret_cast<const uint32_t*>(sm + A_P_OFF);

    fillV(0); cp_commit();
    for (int c = 0; c < 8; c++) {
        if (c + 1 < 8) fillV(c + 1);
        cp_commit();
        cp_wait<1>();
        __syncthreads();

        const uint32_t vs = stg0 + (c & 1) * A_STG;
        float o[2][8][4];
#pragma unroll
        for (int mi = 0; mi < 2; mi++)
#pragma unroll
            for (int nj = 0; nj < 8; nj++)
#pragma unroll
                for (int r = 0; r < 4; r++) o[mi][nj][r] = 0.0f;

#pragma unroll
        for (int kk = 0; kk < 8; kk++) {
            const int kw = kk * 8;
            uint32_t a[2][4];
#pragma unroll
            for (int mi = 0; mi < 2; mi++) {
                int m0 = wm + mi * 16 + g;
                a[mi][0] = pp[m0 * 68 + kw + tig];
                a[mi][1] = pp[(m0 + 8) * 68 + kw + tig];
                a[mi][2] = pp[m0 * 68 + kw + tig + 4];
                a[mi][3] = pp[(m0 + 8) * 68 + kw + tig + 4];
            }
            uint32_t b[8][2];
#pragma unroll
            for (int np = 0; np < 4; np++) {
                int krow = kk * 16 + (lane & 7) + ((lane >> 3) & 1) * 8;
                int col = wn + np * 16 + ((lane >> 4) & 1) * 8;
                ldsm_x4_t(b[np * 2][0], b[np * 2][1], b[np * 2 + 1][0], b[np * 2 + 1][1],
                          vs + krow * 272 + col * 2);
            }
#pragma unroll
            for (int mi = 0; mi < 2; mi++)
#pragma unroll
                for (int nj = 0; nj < 8; nj++) mma_f16(o[mi][nj], a[mi], b[nj]);
        }

        // write output chunk (fp16)
#pragma unroll
        for (int mi = 0; mi < 2; mi++) {
            int r0 = blk * 128 + wm + mi * 16 + g;
#pragma unroll
            for (int nj = 0; nj < 8; nj++) {
                int col = c * 128 + wn + nj * 8 + tig * 2;
                *reinterpret_cast<__half2*>(&attn_out[(size_t)r0 * HH + col]) =
                    __floats2half2_rn(o[mi][nj][0], o[mi][nj][1]);
                *reinterpret_cast<__half2*>(&attn_out[(size_t)(r0 + 8) * HH + col]) =
                    __floats2half2_rn(o[mi][nj][2], o[mi][nj][3]);
            }
        }
        __syncthreads();
    }
}

// ---------------------------------------------------------------------------
extern "C" void kernel_launch(void* const* d_in, const int* in_sizes, int n_in,
                              void* d_out, int out_size) {
    const float* x    = (const float*)d_in[0];
    const float* Wqkv = (const float*)d_in[1];
    const float* Wout = (const float*)d_in[2];
    const float* bout = (const float*)d_in[3];
    float* out = (float*)d_out;

    __half *qkvh, *attnh, *xh, *wqkvt, *wouth;
    cudaGetSymbolAddress((void**)&qkvh, g_qkvh);
    cudaGetSymbolAddress((void**)&attnh, g_attnh);
    cudaGetSymbolAddress((void**)&xh, g_xh);
    cudaGetSymbolAddress((void**)&wqkvt, g_wqkvt);
    cudaGetSymbolAddress((void**)&wouth, g_wouth);

    // conversions
    cvt_half_kernel<<<2048, 256>>>(x, xh, (NTOK * EE) / 4);
    transpose_cvt_kernel<<<dim3(QKV_LD / 32, EE / 32), dim3(32, 8)>>>(
        Wqkv, wqkvt, EE, QKV_LD);
    cvt_half_kernel<<<512, 256>>>(Wout, wouth, (HH * HH) / 4);

    // GEMM1: qkvh = xh @ wqkvt^T   [16384, 3072] (fp16 out)
    {
        cudaFuncSetAttribute(hgemm_kernel<true, false>,
                             cudaFuncAttributeMaxDynamicSharedMemorySize, G_SMEM);
        dim3 grid(QKV_LD / 256, NTOK / 128);   // (12, 128)
        hgemm_kernel<true, false><<<grid, 256, G_SMEM>>>(
            xh, wqkvt, nullptr, qkvh, NTOK, QKV_LD, EE);
    }

    // Attention (tensor-core, fp32 softmax, fp16 out)
    {
        cudaFuncSetAttribute(attn_tc_kernel,
                             cudaFuncAttributeMaxDynamicSharedMemorySize, A_SMEM);
        attn_tc_kernel<<<BB * (SS / 128), 256, A_SMEM>>>(qkvh, attnh);
    }

    // GEMM3: out = attnh @ wouth^T + bout   [16384, 1024] (fp32 out)
    {
        cudaFuncSetAttribute(hgemm_kernel<false, true>,
                             cudaFuncAttributeMaxDynamicSharedMemorySize, G_SMEM);
        dim3 grid(HH / 256, NTOK / 128);       // (4, 128)
        hgemm_kernel<false, true><<<grid, 256, G_SMEM>>>(
            attnh, wouth, bout, out, NTOK, HH, HH);
    }
}